// round 9
// baseline (speedup 1.0000x reference)
#include <cuda_runtime.h>
#include <math.h>

#define VOCABN 30000
#define DN 100
#define RN 150
#define RWN 50
#define SN 50
#define CN 20
#define BN 256
#define LN 512
#define VR 4              // vocab rows per k1-role block
#define K1BLOCKS (VOCABN / VR)   // 7500
#define K0BLOCKS 32
#define WIN 68            // k2 shared window stride in floats (272B)

typedef unsigned long long ull;

// ---- folded constants / tables (static device memory) ----
__device__ float g_Tv[VOCABN * RN];    // blended V embedding per vocab id
__device__ float g_Trw[VOCABN * SN];   // (Tv*Cvs)@Wrs1 + bs1 per vocab id
__device__ float g_wild[SN * SN];      // [s][t]
__device__ float g_S2cT[RN * SN];      // S2[t][r]*Cvs[r], stored [r][t]
__device__ float g_SC[CN * 200];       // [c][0:150]=C_embed*u | [c][150:200]=C_w*uw

// ---- packed f32x2 helpers ----
__device__ __forceinline__ ull FMA2(ull a, ull b, ull c) {
    ull d;
    asm("fma.rn.f32x2 %0, %1, %2, %3;" : "=l"(d) : "l"(a), "l"(b), "l"(c));
    return d;
}
__device__ __forceinline__ float HSUM2(ull a, ull b) {
    union { ull u; float2 f; } x, y;
    x.u = a; y.u = b;
    return (x.f.x + x.f.y) + (y.f.x + y.f.y);
}
__device__ __forceinline__ ull PACK2(float a, float b) {
    union { ull u; float2 f; } x;
    x.f = make_float2(a, b);
    return x.u;
}

// Uniform half-dot: 13 packed pairs (26 floats) from 16B-aligned shared.
// 6 LDS.128 + 1 LDS.64 + 13 fma.f32x2, two accumulator chains of depth 6-7.
// Half-0 threads carry a zero 13th weight so both halves run identical code.
__device__ __forceinline__ float dot13(const float* __restrict__ a,
                                       const ull* __restrict__ w) {
    ull acc0 = 0ull, acc1 = 0ull;
#pragma unroll
    for (int j = 0; j < 6; j++) {
        ulonglong2 v = *(const ulonglong2*)(a + 4 * j);
        acc0 = FMA2(w[2 * j], v.x, acc0);
        acc1 = FMA2(w[2 * j + 1], v.y, acc1);
    }
    acc0 = FMA2(w[12], *(const ull*)(a + 24), acc0);
    return HSUM2(acc0, acc1);
}

// ---------------------------------------------------------------------------
// k01: merged constant-folding (k0 role, 32 blocks) + vocab tables (k1 role,
// 7500 blocks, 4 rows each). k1 blocks compute Cvs locally (20 adds), so the
// two roles are independent -> single launch.
// ---------------------------------------------------------------------------
__global__ void __launch_bounds__(160)
k01(const float* __restrict__ C_embed, const float* __restrict__ C_w,
    const float* __restrict__ S1w, const float* __restrict__ S2w,
    const float* __restrict__ WW, const float* __restrict__ hT,
    const float* __restrict__ S2,
    const float* __restrict__ W_embed, const float* __restrict__ embed_r,
    const float* __restrict__ V_embed, const float* __restrict__ beta,
    const float* __restrict__ Wrs1, const float* __restrict__ bs1) {
    __shared__ float sm[VR * DN + VR * RN];   // k1: w4 | q4
    __shared__ float k0sm[RN + RN + RWN + RWN]; // k0: cvs | u | cw | uw
    int t = threadIdx.x;

    if (blockIdx.x >= K1BLOCKS) {
        // ------------------- k0 role -------------------
        float* cvs = k0sm;
        float* u   = k0sm + RN;
        float* cw  = k0sm + 2 * RN;
        float* uw  = k0sm + 2 * RN + RWN;
        if (t < RN) {
            float s = 0.f;
#pragma unroll
            for (int c = 0; c < CN; c++) s += C_embed[c * RN + t];
            cvs[t] = s;
            float su = 0.f;
#pragma unroll
            for (int s2 = 0; s2 < SN; s2++) su += hT[s2] * S2[s2 * RN + t];
            u[t] = su;
        }
        if (t < RWN) {
            float s = 0.f;
#pragma unroll
            for (int c = 0; c < CN; c++) s += C_w[c * RWN + t];
            cw[t] = s;
            float su = 0.f;
#pragma unroll
            for (int s2 = 0; s2 < SN; s2++) su += hT[s2] * S2w[s2 * RWN + t];
            uw[t] = su;
        }
        __syncthreads();

        const int N_WLD = SN * SN;            // 2500
        const int N_S2C = RN * SN;            // 7500
        const int N_SC  = CN * 200;           // 4000
        const int TOT = N_WLD + N_S2C + N_SC;
        int bid = blockIdx.x - K1BLOCKS;
        int stride = K0BLOCKS * 160;
        for (int g = bid * 160 + t; g < TOT; g += stride) {
            int i = g;
            if (i < N_WLD) {
                int s = i / SN, tt = i % SN;
                float acc = WW[i];
#pragma unroll
                for (int r = 0; r < RWN; r++)
                    acc += S1w[s * RWN + r] * cw[r] * S2w[tt * RWN + r];
                g_wild[i] = acc;
                continue;
            }
            i -= N_WLD;
            if (i < N_S2C) {
                int r = i / SN, tt = i % SN;
                g_S2cT[i] = S2[tt * RN + r] * cvs[r];
                continue;
            }
            i -= N_S2C;
            {
                int c = i / 200, k = i % 200;
                g_SC[i] = (k < RN) ? C_embed[c * RN + k] * u[k]
                                   : C_w[c * RWN + (k - RN)] * uw[k - RN];
            }
        }
        return;
    }

    // ------------------- k1 role -------------------
    float* w4 = sm;                    // 4 consecutive W_embed rows
    float (*q4)[RN] = (float (*)[RN])(sm + VR * DN);
    int v0 = blockIdx.x * VR;

    for (int i = t; i < VR * DN; i += 160)
        w4[i] = W_embed[v0 * DN + i];
    __syncthreads();

    if (t < RN) {
        // local Cvs
        float cv = 0.f;
#pragma unroll
        for (int c = 0; c < CN; c++) cv += C_embed[c * RN + t];

        float a0 = 0.f, a1 = 0.f, a2 = 0.f, a3 = 0.f;
#pragma unroll 4
        for (int d = 0; d < DN; d++) {
            float e = embed_r[d * RN + t];
            a0 += e * w4[0 * DN + d];
            a1 += e * w4[1 * DN + d];
            a2 += e * w4[2 * DN + d];
            a3 += e * w4[3 * DN + d];
        }
        float b = beta[t];
        float acc[VR] = {a0, a1, a2, a3};
#pragma unroll
        for (int r = 0; r < VR; r++) {
            float th;
            asm("tanh.approx.f32 %0, %1;" : "=f"(th) : "f"(acc[r]));
            float tv = V_embed[(v0 + r) * RN + t] * b + th * (1.f - b);
            g_Tv[(v0 + r) * RN + t] = tv;
            q4[r][t] = tv * cv;
        }
    }
    __syncthreads();

    if (t < SN) {
        float a0 = 0.f, a1 = 0.f, a2 = 0.f, a3 = 0.f;
#pragma unroll 2
        for (int d = 0; d < RN; d++) {
            float wv = Wrs1[d * SN + t];
            a0 += wv * q4[0][d];
            a1 += wv * q4[1][d];
            a2 += wv * q4[2][d];
            a3 += wv * q4[3][d];
        }
        float bb = bs1[t];
        g_Trw[(v0 + 0) * SN + t] = bb + a0;
        g_Trw[(v0 + 1) * SN + t] = bb + a1;
        g_Trw[(v0 + 2) * SN + t] = bb + a2;
        g_Trw[(v0 + 3) * SN + t] = bb + a3;
    }
}

// ---------------------------------------------------------------------------
// k2: sequential recurrence. 128 CTAs x 576 threads (18 warps = 4.5/SMSP),
// 2 batch chains per CTA in f32x2 lanes (SoA act_x/act_y).
// Every 50-dot is split across a LANE PAIR: half0 = k[0,24), half1 = k[24,50),
// both executed as a uniform dot13 (half0's 13th weight = 0), combined with
// one shfl_xor(1).
//
// Shared windows (stride WIN=68 floats = 272B, bases pairwise-distinct
// mod 128B): hbuf0 @0, hbuf1 @68, p0 @136, p1 @204, p2 @272, aw @340.
//
// Phase 1 (t<512): roles r1=t>>1: r1<150 -> p[r1]; 150..199 -> aw; 200..249
//   -> gate gz. Phase 2 (all): roles m2=t>>1: m2<200 -> h_new chunk
//   (3x S2cT + 1x wild); 200..279 -> score chunk. 8 partials/output reduced
//   with shfl_xor 1,2,4; lane t%8==0 writes. Double-buffered h; 2 bars/step;
//   next-step Tv/Trw gathers prefetched at phase-2 start.
// ---------------------------------------------------------------------------
__global__ void __launch_bounds__(576, 1)
k2_recur(const int* __restrict__ tokens,
         const float* __restrict__ S1,
         const float* __restrict__ S1w,
         const float* __restrict__ Wss1,
         const float* __restrict__ h0,
         const float* __restrict__ prio_a,
         const float* __restrict__ prio_b,
         float* __restrict__ out) {
    __shared__ __align__(16) float act_x[6 * WIN];
    __shared__ __align__(16) float act_y[6 * WIN];
    __shared__ float2 gz[SN];
    __shared__ int s_ntok[2];

    int t = threadIdx.x;
    int b0 = blockIdx.x * 2;
    int b1 = b0 + 1;
    int tb0 = b0 * LN, tb1 = b1 * LN;
    long ob0 = (long)b0 * LN * CN, ob1 = (long)b1 * LN * CN;

    int r1 = t >> 1;       // role (phase-1 == phase-2 indexing base)
    int h1 = t & 1;        // half within the lane pair
    int kk0 = 24 * h1;     // k-offset of this half

    // ---- phase-1 weights ----
    ull wA[13];
#pragma unroll
    for (int j = 0; j < 13; j++) wA[j] = 0ull;
    int p1w = 0;
    if (t < 500) {
        const float* mA;
        int strA, colA;
        if (r1 < 150) {
            mA = S1; strA = RN; colA = r1;
            p1w = (2 + r1 / 50) * WIN + (r1 % 50);
        } else if (r1 < 200) {
            mA = S1w; strA = RWN; colA = r1 - 150;
        } else {
            mA = Wss1; strA = SN; colA = r1 - 200;
        }
#pragma unroll
        for (int j = 0; j < 12; j++)
            wA[j] = PACK2(mA[(kk0 + 2 * j) * strA + colA],
                          mA[(kk0 + 2 * j + 1) * strA + colA]);
        if (h1) wA[12] = PACK2(mA[48 * strA + colA], mA[49 * strA + colA]);
    }

    // ---- phase-2 weights ----
    ull wB[13];
#pragma unroll
    for (int j = 0; j < 13; j++) wB[j] = 0ull;
    int aoffB = 0;
    bool useHc = false;
    if (r1 < 200) {
        int tt = r1 >> 2, q2 = r1 & 3;
        const float* src;
        int str;
        if (q2 < 3) { src = g_S2cT + q2 * 50 * SN + tt; str = SN; aoffB = (2 + q2) * WIN; }
        else        { src = g_wild + tt;               str = SN; useHc = true; }
#pragma unroll
        for (int j = 0; j < 12; j++)
            wB[j] = PACK2(src[(kk0 + 2 * j) * str], src[(kk0 + 2 * j + 1) * str]);
        if (h1) wB[12] = PACK2(src[48 * str], src[49 * str]);
    } else if (r1 < 280) {
        int c = (r1 - 200) >> 2, q2 = (r1 - 200) & 3;
        int base = c * 200 + (q2 < 3 ? q2 * 50 : 150);
#pragma unroll
        for (int j = 0; j < 12; j++)
            wB[j] = PACK2(g_SC[base + kk0 + 2 * j], g_SC[base + kk0 + 2 * j + 1]);
        if (h1) wB[12] = PACK2(g_SC[base + 48], g_SC[base + 49]);
        aoffB = (q2 < 3) ? (2 + q2) * WIN : 5 * WIN;
    }

    float pa = 0.f, pb = 0.f;
    if ((t & 7) == 0 && t >= 400 && t < 560) {
        int c = (t - 400) >> 3;
        pa = prio_a[c]; pb = prio_b[c];
    }

    // ---- init: state + prime step-0 gathers ----
    if (t < SN) { float h = h0[t]; act_x[t] = h; act_y[t] = h; }
    float tvx = 0.f, tvy = 0.f, trx = 0.f, tryy = 0.f;
    {
        int t0 = tokens[tb0], t1 = tokens[tb1];
        if (h1 == 0) {
            if (r1 < 150) {
                tvx = g_Tv[t0 * RN + r1];
                tvy = g_Tv[t1 * RN + r1];
            } else if (r1 >= 200 && r1 < 250) {
                trx  = g_Trw[t0 * SN + (r1 - 200)];
                tryy = g_Trw[t1 * SN + (r1 - 200)];
            }
        }
    }
    __syncthreads();

    for (int l = 0; l < LN; l++) {
        int hc = (l & 1) ? WIN : 0;

        // ---------------- phase 1: half-dots over h ----------------
        if (t < 512) {           // whole warps 0..15 (uniform shuffles)
            float ax = dot13(act_x + hc + kk0, wA);
            float ay = dot13(act_y + hc + kk0, wA);
            ax += __shfl_xor_sync(0xffffffffu, ax, 1);
            ay += __shfl_xor_sync(0xffffffffu, ay, 1);
            if (h1 == 0 && r1 < 250) {
                if (r1 < 150) {
                    act_x[p1w] = ax * tvx;
                    act_y[p1w] = ay * tvy;
                } else if (r1 < 200) {
                    act_x[5 * WIN + (r1 - 150)] = ax;
                    act_y[5 * WIN + (r1 - 150)] = ay;
                } else {
                    float zx = 1.f / (1.f + __expf(-(ax + trx)));
                    float zy = 1.f / (1.f + __expf(-(ay + tryy)));
                    gz[r1 - 200] = make_float2(zx, zy);
                }
            }
        } else if (t == 560) {
            int nl = (l + 1 < LN) ? l + 1 : l;
            s_ntok[0] = tokens[tb0 + nl];
        } else if (t == 561) {
            int nl = (l + 1 < LN) ? l + 1 : l;
            s_ntok[1] = tokens[tb1 + nl];
        }
        __syncthreads();

        // ------ phase 2: chunk half-dots + reduce + writeback + prefetch ----
        {
            int n0 = s_ntok[0], n1 = s_ntok[1];
            if (h1 == 0) {
                if (r1 < 150) {
                    tvx = g_Tv[n0 * RN + r1];
                    tvy = g_Tv[n1 * RN + r1];
                } else if (r1 >= 200 && r1 < 250) {
                    trx  = g_Trw[n0 * SN + (r1 - 200)];
                    tryy = g_Trw[n1 * SN + (r1 - 200)];
                }
            }

            int a2 = useHc ? hc : aoffB;
            float sx = dot13(act_x + a2 + kk0, wB);
            float sy = dot13(act_y + a2 + kk0, wB);

            sx += __shfl_xor_sync(0xffffffffu, sx, 1);
            sx += __shfl_xor_sync(0xffffffffu, sx, 2);
            sx += __shfl_xor_sync(0xffffffffu, sx, 4);
            sy += __shfl_xor_sync(0xffffffffu, sy, 1);
            sy += __shfl_xor_sync(0xffffffffu, sy, 2);
            sy += __shfl_xor_sync(0xffffffffu, sy, 4);

            if ((t & 7) == 0 && t < 560) {
                if (t < 400) {
                    int tt = t >> 3;
                    int hn = WIN - hc;
                    float2 z = gz[tt];
                    float hox = act_x[hc + tt], hoy = act_y[hc + tt];
                    act_x[hn + tt] = z.x * sx + (1.f - z.x) * hox;
                    act_y[hn + tt] = z.y * sy + (1.f - z.y) * hoy;
                } else {
                    int c = (t - 400) >> 3;
                    out[ob0 + (long)l * CN + c] = sx * pa + pb;
                    out[ob1 + (long)l * CN + c] = sy * pa + pb;
                }
            }
        }
        __syncthreads();
    }
}

// ---------------------------------------------------------------------------
// Launch. Inputs (metadata order): tokens, W_embed, embed_r, V_embed,
// C_embed, S1, S2, S1_w, S2_w, C_w, WW, h0, hT, beta_vec, Wss1, Wrs1, bs1,
// prio_a, prio_b
// ---------------------------------------------------------------------------
extern "C" void kernel_launch(void* const* d_in, const int* in_sizes, int n_in,
                              void* d_out, int out_size) {
    const int*   tokens  = (const int*)  d_in[0];
    const float* W_embed = (const float*)d_in[1];
    const float* embed_r = (const float*)d_in[2];
    const float* V_embed = (const float*)d_in[3];
    const float* C_embed = (const float*)d_in[4];
    const float* S1      = (const float*)d_in[5];
    const float* S2      = (const float*)d_in[6];
    const float* S1_w    = (const float*)d_in[7];
    const float* S2_w    = (const float*)d_in[8];
    const float* C_w     = (const float*)d_in[9];
    const float* WW      = (const float*)d_in[10];
    const float* h0      = (const float*)d_in[11];
    const float* hT      = (const float*)d_in[12];
    const float* beta    = (const float*)d_in[13];
    const float* Wss1    = (const float*)d_in[14];
    const float* Wrs1    = (const float*)d_in[15];
    const float* bs1     = (const float*)d_in[16];
    const float* prio_a  = (const float*)d_in[17];
    const float* prio_b  = (const float*)d_in[18];
    float* out = (float*)d_out;

    k01<<<K1BLOCKS + K0BLOCKS, 160>>>(C_embed, C_w, S1_w, S2_w, WW, hT, S2,
                                      W_embed, embed_r, V_embed, beta, Wrs1, bs1);
    k2_recur<<<BN / 2, 576>>>(tokens, S1, S1_w, Wss1, h0, prio_a, prio_b, out);
}

// round 10
// speedup vs baseline: 1.5215x; 1.5215x over previous
#include <cuda_runtime.h>
#include <math.h>

#define VOCABN 30000
#define DN 100
#define RN 150
#define RWN 50
#define SN 50
#define CN 20
#define BN 256
#define LN 512
#define VR 8                      // vocab rows per k1-role block
#define K1BLOCKS (VOCABN / VR)    // 3750
#define K0BLOCKS 32
#define WIN 68                    // k2 shared window stride (272B)

typedef unsigned long long ull;

// ---- folded constants / tables (static device memory) ----
__device__ float g_Tv[VOCABN * RN];    // blended V embedding per vocab id
__device__ float g_Trw[VOCABN * SN];   // (Tv*Cvs)@Wrs1 + bs1 per vocab id
__device__ float g_wild[SN * SN];      // [s][t]
__device__ float g_S2cT[RN * SN];      // S2[t][r]*Cvs[r], stored [r][t]
__device__ float g_SC[CN * 200];       // [c][0:150]=C_embed*u | [c][150:200]=C_w*uw

// ---- packed f32x2 helpers ----
__device__ __forceinline__ ull FMA2(ull a, ull b, ull c) {
    ull d;
    asm("fma.rn.f32x2 %0, %1, %2, %3;" : "=l"(d) : "l"(a), "l"(b), "l"(c));
    return d;
}
__device__ __forceinline__ float HSUM2(ull a, ull b) {
    union { ull u; float2 f; } x, y;
    x.u = a; y.u = b;
    return (x.f.x + x.f.y) + (y.f.x + y.f.y);
}
__device__ __forceinline__ ull PACK2(float a, float b) {
    union { ull u; float2 f; } x;
    x.f = make_float2(a, b);
    return x.u;
}
__device__ __forceinline__ float SIG(float v) {
    return 1.f / (1.f + __expf(-v));
}

// G=2 dual-output, dual-chain 50-dot. Activations loaded ONCE (26 LDS.128)
// and reused for both output columns: 100 fma.f32x2 per 26 loads.
__device__ __forceinline__ void dot50x2(const float* __restrict__ ax,
                                        const float* __restrict__ ay,
                                        const ull* __restrict__ w1,
                                        const ull* __restrict__ w2,
                                        float& o0x, float& o0y,
                                        float& o1x, float& o1y) {
    ull a0x = 0, a1x = 0, b0x = 0, b1x = 0;
    ull a0y = 0, a1y = 0, b0y = 0, b1y = 0;
#pragma unroll
    for (int j = 0; j < 6; j++) {
        ulonglong2 vx0 = *(const ulonglong2*)(ax + 8 * j);
        ulonglong2 vx1 = *(const ulonglong2*)(ax + 8 * j + 4);
        ulonglong2 vy0 = *(const ulonglong2*)(ay + 8 * j);
        ulonglong2 vy1 = *(const ulonglong2*)(ay + 8 * j + 4);
        a0x = FMA2(w1[4 * j + 0], vx0.x, a0x);
        a1x = FMA2(w1[4 * j + 1], vx0.y, a1x);
        a0x = FMA2(w1[4 * j + 2], vx1.x, a0x);
        a1x = FMA2(w1[4 * j + 3], vx1.y, a1x);
        b0x = FMA2(w2[4 * j + 0], vx0.x, b0x);
        b1x = FMA2(w2[4 * j + 1], vx0.y, b1x);
        b0x = FMA2(w2[4 * j + 2], vx1.x, b0x);
        b1x = FMA2(w2[4 * j + 3], vx1.y, b1x);
        a0y = FMA2(w1[4 * j + 0], vy0.x, a0y);
        a1y = FMA2(w1[4 * j + 1], vy0.y, a1y);
        a0y = FMA2(w1[4 * j + 2], vy1.x, a0y);
        a1y = FMA2(w1[4 * j + 3], vy1.y, a1y);
        b0y = FMA2(w2[4 * j + 0], vy0.x, b0y);
        b1y = FMA2(w2[4 * j + 1], vy0.y, b1y);
        b0y = FMA2(w2[4 * j + 2], vy1.x, b0y);
        b1y = FMA2(w2[4 * j + 3], vy1.y, b1y);
    }
    ull tx = *(const ull*)(ax + 48);
    ull ty = *(const ull*)(ay + 48);
    a0x = FMA2(w1[24], tx, a0x);
    b0x = FMA2(w2[24], tx, b0x);
    a0y = FMA2(w1[24], ty, a0y);
    b0y = FMA2(w2[24], ty, b0y);
    o0x = HSUM2(a0x, a1x);
    o1x = HSUM2(b0x, b1x);
    o0y = HSUM2(a0y, a1y);
    o1y = HSUM2(b0y, b1y);
}

// ---------------------------------------------------------------------------
// k01: merged constant folding (k0 role, 32 blocks) + vocab tables
// (k1 role, 3750 blocks x 8 vocab rows).
// ---------------------------------------------------------------------------
__global__ void __launch_bounds__(160)
k01(const float* __restrict__ C_embed, const float* __restrict__ C_w,
    const float* __restrict__ S1w, const float* __restrict__ S2w,
    const float* __restrict__ WW, const float* __restrict__ hT,
    const float* __restrict__ S2,
    const float* __restrict__ W_embed, const float* __restrict__ embed_r,
    const float* __restrict__ V_embed, const float* __restrict__ beta,
    const float* __restrict__ Wrs1, const float* __restrict__ bs1) {
    __shared__ float sm[VR * DN + VR * RN];     // k1: w rows | q rows
    __shared__ float k0sm[2 * RN + 2 * RWN];    // k0: cvs | u | cw | uw
    int t = threadIdx.x;

    if (blockIdx.x >= K1BLOCKS) {
        // ---------------- k0 role ----------------
        float* cvs = k0sm;
        float* u   = k0sm + RN;
        float* cw  = k0sm + 2 * RN;
        float* uw  = k0sm + 2 * RN + RWN;
        if (t < RN) {
            float s = 0.f;
#pragma unroll
            for (int c = 0; c < CN; c++) s += C_embed[c * RN + t];
            cvs[t] = s;
            float su = 0.f;
#pragma unroll
            for (int s2 = 0; s2 < SN; s2++) su += hT[s2] * S2[s2 * RN + t];
            u[t] = su;
        }
        if (t < RWN) {
            float s = 0.f;
#pragma unroll
            for (int c = 0; c < CN; c++) s += C_w[c * RWN + t];
            cw[t] = s;
            float su = 0.f;
#pragma unroll
            for (int s2 = 0; s2 < SN; s2++) su += hT[s2] * S2w[s2 * RWN + t];
            uw[t] = su;
        }
        __syncthreads();

        const int N_WLD = SN * SN;
        const int N_S2C = RN * SN;
        const int N_SC  = CN * 200;
        const int TOT = N_WLD + N_S2C + N_SC;
        int bid = blockIdx.x - K1BLOCKS;
        int stride = K0BLOCKS * 160;
        for (int g = bid * 160 + t; g < TOT; g += stride) {
            int i = g;
            if (i < N_WLD) {
                int s = i / SN, tt = i % SN;
                float acc = WW[i];
#pragma unroll
                for (int r = 0; r < RWN; r++)
                    acc += S1w[s * RWN + r] * cw[r] * S2w[tt * RWN + r];
                g_wild[i] = acc;
                continue;
            }
            i -= N_WLD;
            if (i < N_S2C) {
                int r = i / SN, tt = i % SN;
                g_S2cT[i] = S2[tt * RN + r] * cvs[r];
                continue;
            }
            i -= N_S2C;
            {
                int c = i / 200, k = i % 200;
                g_SC[i] = (k < RN) ? C_embed[c * RN + k] * u[k]
                                   : C_w[c * RWN + (k - RN)] * uw[k - RN];
            }
        }
        return;
    }

    // ---------------- k1 role ----------------
    float* w8 = sm;                                  // VR rows of W_embed
    float (*q8)[RN] = (float (*)[RN])(sm + VR * DN); // tv * Cvs per row
    int v0 = blockIdx.x * VR;

    for (int i = t; i < VR * DN; i += 160)
        w8[i] = W_embed[v0 * DN + i];
    __syncthreads();

    if (t < RN) {
        float cv = 0.f;
#pragma unroll
        for (int c = 0; c < CN; c++) cv += C_embed[c * RN + t];

        float acc[VR];
#pragma unroll
        for (int r = 0; r < VR; r++) acc[r] = 0.f;
#pragma unroll 2
        for (int d = 0; d < DN; d++) {
            float e = embed_r[d * RN + t];
#pragma unroll
            for (int r = 0; r < VR; r++) acc[r] += e * w8[r * DN + d];
        }
        float b = beta[t];
#pragma unroll
        for (int r = 0; r < VR; r++) {
            float th;
            asm("tanh.approx.f32 %0, %1;" : "=f"(th) : "f"(acc[r]));
            float tv = V_embed[(v0 + r) * RN + t] * b + th * (1.f - b);
            g_Tv[(v0 + r) * RN + t] = tv;
            q8[r][t] = tv * cv;
        }
    }
    __syncthreads();

    if (t < SN) {
        float acc[VR];
#pragma unroll
        for (int r = 0; r < VR; r++) acc[r] = 0.f;
#pragma unroll 2
        for (int d = 0; d < RN; d++) {
            float wv = Wrs1[d * SN + t];
#pragma unroll
            for (int r = 0; r < VR; r++) acc[r] += wv * q8[r][d];
        }
        float bb = bs1[t];
#pragma unroll
        for (int r = 0; r < VR; r++)
            g_Trw[(v0 + r) * SN + t] = bb + acc[r];
    }
}

// ---------------------------------------------------------------------------
// k2: sequential recurrence. 128 CTAs x 288 threads, 2 batch chains per CTA
// (SoA act_x/act_y). WARP-SPECIALIZED, G=2:
//   warps 0-3 (t<128, 125 active): phase-1. Thread owns 2 weight columns
//     (outs 2t,2t+1) of {S1|S1_w|Wss1}; computes 2 full 50-dots x 2 chains
//     per activation load; writes p/aw/gz directly (no reduction).
//     During phase-2 it prefetches next step's Tv/Trw.
//   warps 4-8 (i=t-128, 140 active): phase-2. Thread owns chunk q=i&3 of
//     outputs o0=2*(i>>2), o0+1 (o<50: h_new, o>=50: score). 4 chunk
//     partials per output reduced with shfl_xor(1,2); lane q==0 blends the
//     gate and writes h / scores. Pre-phase-1 it loads next tokens.
//
// Shared windows (stride WIN=68 floats; bases pairwise distinct mod 128B):
//   h0 @0, h1 @WIN (double buffer), p0/p1/p2 @(2..4)*WIN, aw @5*WIN.
// 2 barriers/step.
// ---------------------------------------------------------------------------
__global__ void __launch_bounds__(288, 1)
k2_recur(const int* __restrict__ tokens,
         const float* __restrict__ S1,
         const float* __restrict__ S1w,
         const float* __restrict__ Wss1,
         const float* __restrict__ h0,
         const float* __restrict__ prio_a,
         const float* __restrict__ prio_b,
         float* __restrict__ out) {
    __shared__ __align__(16) float act_x[6 * WIN];
    __shared__ __align__(16) float act_y[6 * WIN];
    __shared__ __align__(16) float2 gz[SN];
    __shared__ int s_ntok[2];

    int t = threadIdx.x;
    int b0 = blockIdx.x * 2;
    int b1 = b0 + 1;
    int tb0 = b0 * LN, tb1 = b1 * LN;
    long ob0 = (long)b0 * LN * CN, ob1 = (long)b1 * LN * CN;

    ull w1[25], w2[25];
#pragma unroll
    for (int j = 0; j < 25; j++) { w1[j] = 0ull; w2[j] = 0ull; }

    const bool isP1 = (t < 128);

    // phase-1 role state
    int fam = 3;         // 0=p, 1=aw, 2=gate, 3=inactive
    int p1w = 0;         // write base for p/aw
    int out0 = 0;
    // phase-2 role state
    int q2 = 0, o0 = 0;
    bool isScore = false, winIsH = false, p2w = false;
    int winOff = 0;
    float2 paA = make_float2(0.f, 0.f), pbA = make_float2(0.f, 0.f);

    if (isP1) {
        if (t < 125) {
            out0 = 2 * t;
            const float* mA;
            int strA, col0;
            if (out0 < 150)      { fam = 0; mA = S1;   strA = RN;  col0 = out0;
                                   p1w = (2 + out0 / 50) * WIN + (out0 % 50); }
            else if (out0 < 200) { fam = 1; mA = S1w;  strA = RWN; col0 = out0 - 150;
                                   p1w = 5 * WIN + (out0 - 150); }
            else                 { fam = 2; mA = Wss1; strA = SN;  col0 = out0 - 200; }
#pragma unroll
            for (int j = 0; j < 25; j++) {
                w1[j] = PACK2(mA[(2 * j) * strA + col0],
                              mA[(2 * j + 1) * strA + col0]);
                w2[j] = PACK2(mA[(2 * j) * strA + col0 + 1],
                              mA[(2 * j + 1) * strA + col0 + 1]);
            }
        }
    } else {
        int i = t - 128;
        q2 = i & 3;
        int og = i >> 2;
        o0 = 2 * og;
        p2w = (q2 == 0) && (i < 140);
        if (og < 25) {
            // h_new chunk
            if (q2 < 3) {
                const float* P = g_S2cT + q2 * 50 * SN;
                winOff = (2 + q2) * WIN;
#pragma unroll
                for (int j = 0; j < 25; j++) {
                    w1[j] = PACK2(P[(2 * j) * SN + o0], P[(2 * j + 1) * SN + o0]);
                    w2[j] = PACK2(P[(2 * j) * SN + o0 + 1], P[(2 * j + 1) * SN + o0 + 1]);
                }
            } else {
                winIsH = true;
#pragma unroll
                for (int j = 0; j < 25; j++) {
                    w1[j] = PACK2(g_wild[(2 * j) * SN + o0], g_wild[(2 * j + 1) * SN + o0]);
                    w2[j] = PACK2(g_wild[(2 * j) * SN + o0 + 1], g_wild[(2 * j + 1) * SN + o0 + 1]);
                }
            }
        } else if (og < 35) {
            isScore = true;
            int c0 = o0 - 50;
            int off = (q2 < 3) ? q2 * 50 : 150;
            winOff = (q2 < 3) ? (2 + q2) * WIN : 5 * WIN;
#pragma unroll
            for (int j = 0; j < 25; j++) {
                w1[j] = PACK2(g_SC[c0 * 200 + off + 2 * j],
                              g_SC[c0 * 200 + off + 2 * j + 1]);
                w2[j] = PACK2(g_SC[(c0 + 1) * 200 + off + 2 * j],
                              g_SC[(c0 + 1) * 200 + off + 2 * j + 1]);
            }
            if (p2w) {
                paA = make_float2(prio_a[c0], prio_a[c0 + 1]);
                pbA = make_float2(prio_b[c0], prio_b[c0 + 1]);
            }
        }
        // i >= 140: zero weights, winOff=0 (valid reads), no writes
    }

    // ---- init: state + prime step-0 gathers ----
    if (t < SN) { float h = h0[t]; act_x[t] = h; act_y[t] = h; }
    float2 tvA = make_float2(0.f, 0.f), tvB = tvA, trA = tvA, trB = tvA;
    if (isP1 && fam != 3) {
        int t0 = tokens[tb0], t1 = tokens[tb1];
        if (fam == 0) {
            tvA = *(const float2*)&g_Tv[t0 * RN + out0];
            tvB = *(const float2*)&g_Tv[t1 * RN + out0];
        } else if (fam == 2) {
            trA = *(const float2*)&g_Trw[t0 * SN + (out0 - 200)];
            trB = *(const float2*)&g_Trw[t1 * SN + (out0 - 200)];
        }
    }
    __syncthreads();

    for (int l = 0; l < LN; l++) {
        int hc = (l & 1) ? WIN : 0;

        // ------------- interval A: phase-1 compute | token preload -------------
        if (isP1) {
            if (fam != 3) {
                float o0x, o0y, o1x, o1y;
                dot50x2(act_x + hc, act_y + hc, w1, w2, o0x, o0y, o1x, o1y);
                if (fam == 0) {
                    *(float2*)&act_x[p1w] = make_float2(o0x * tvA.x, o1x * tvA.y);
                    *(float2*)&act_y[p1w] = make_float2(o0y * tvB.x, o1y * tvB.y);
                } else if (fam == 1) {
                    *(float2*)&act_x[p1w] = make_float2(o0x, o1x);
                    *(float2*)&act_y[p1w] = make_float2(o0y, o1y);
                } else {
                    float z0x = SIG(o0x + trA.x), z1x = SIG(o1x + trA.y);
                    float z0y = SIG(o0y + trB.x), z1y = SIG(o1y + trB.y);
                    *(float4*)&gz[out0 - 200] = make_float4(z0x, z0y, z1x, z1y);
                }
            }
        } else {
            int nl = (l + 1 < LN) ? l + 1 : l;
            if (t == 128) s_ntok[0] = tokens[tb0 + nl];
            if (t == 129) s_ntok[1] = tokens[tb1 + nl];
        }
        __syncthreads();

        // ------------- interval B: phase-2 compute | Tv/Trw prefetch -----------
        if (isP1) {
            if (fam == 0) {
                int n0 = s_ntok[0], n1 = s_ntok[1];
                tvA = *(const float2*)&g_Tv[n0 * RN + out0];
                tvB = *(const float2*)&g_Tv[n1 * RN + out0];
            } else if (fam == 2) {
                int n0 = s_ntok[0], n1 = s_ntok[1];
                trA = *(const float2*)&g_Trw[n0 * SN + (out0 - 200)];
                trB = *(const float2*)&g_Trw[n1 * SN + (out0 - 200)];
            }
        } else {
            int aw2 = winIsH ? hc : winOff;
            float s0x, s0y, s1x, s1y;
            dot50x2(act_x + aw2, act_y + aw2, w1, w2, s0x, s0y, s1x, s1y);

            s0x += __shfl_xor_sync(0xffffffffu, s0x, 1);
            s0x += __shfl_xor_sync(0xffffffffu, s0x, 2);
            s1x += __shfl_xor_sync(0xffffffffu, s1x, 1);
            s1x += __shfl_xor_sync(0xffffffffu, s1x, 2);
            s0y += __shfl_xor_sync(0xffffffffu, s0y, 1);
            s0y += __shfl_xor_sync(0xffffffffu, s0y, 2);
            s1y += __shfl_xor_sync(0xffffffffu, s1y, 1);
            s1y += __shfl_xor_sync(0xffffffffu, s1y, 2);

            if (p2w) {
                if (!isScore) {
                    int hn = WIN - hc;
                    float2 hx = *(const float2*)&act_x[hc + o0];
                    float2 hy = *(const float2*)&act_y[hc + o0];
                    float2 z0 = gz[o0];       // {z_x, z_y} for out o0
                    float2 z1 = gz[o0 + 1];
                    *(float2*)&act_x[hn + o0] = make_float2(
                        z0.x * s0x + (1.f - z0.x) * hx.x,
                        z1.x * s1x + (1.f - z1.x) * hx.y);
                    *(float2*)&act_y[hn + o0] = make_float2(
                        z0.y * s0y + (1.f - z0.y) * hy.x,
                        z1.y * s1y + (1.f - z1.y) * hy.y);
                } else {
                    int c0 = o0 - 50;
                    *(float2*)(out + ob0 + (long)l * CN + c0) =
                        make_float2(s0x * paA.x + pbA.x, s1x * paA.y + pbA.y);
                    *(float2*)(out + ob1 + (long)l * CN + c0) =
                        make_float2(s0y * paA.x + pbA.x, s1y * paA.y + pbA.y);
                }
            }
        }
        __syncthreads();
    }
}

// ---------------------------------------------------------------------------
// Launch. Inputs (metadata order): tokens, W_embed, embed_r, V_embed,
// C_embed, S1, S2, S1_w, S2_w, C_w, WW, h0, hT, beta_vec, Wss1, Wrs1, bs1,
// prio_a, prio_b
// ---------------------------------------------------------------------------
extern "C" void kernel_launch(void* const* d_in, const int* in_sizes, int n_in,
                              void* d_out, int out_size) {
    const int*   tokens  = (const int*)  d_in[0];
    const float* W_embed = (const float*)d_in[1];
    const float* embed_r = (const float*)d_in[2];
    const float* V_embed = (const float*)d_in[3];
    const float* C_embed = (const float*)d_in[4];
    const float* S1      = (const float*)d_in[5];
    const float* S2      = (const float*)d_in[6];
    const float* S1_w    = (const float*)d_in[7];
    const float* S2_w    = (const float*)d_in[8];
    const float* C_w     = (const float*)d_in[9];
    const float* WW      = (const float*)d_in[10];
    const float* h0      = (const float*)d_in[11];
    const float* hT      = (const float*)d_in[12];
    const float* beta    = (const float*)d_in[13];
    const float* Wss1    = (const float*)d_in[14];
    const float* Wrs1    = (const float*)d_in[15];
    const float* bs1     = (const float*)d_in[16];
    const float* prio_a  = (const float*)d_in[17];
    const float* prio_b  = (const float*)d_in[18];
    float* out = (float*)d_out;

    k01<<<K1BLOCKS + K0BLOCKS, 160>>>(C_embed, C_w, S1_w, S2_w, WW, hT, S2,
                                      W_embed, embed_r, V_embed, beta, Wrs1, bs1);
    k2_recur<<<BN / 2, 288>>>(tokens, S1, S1_w, Wss1, h0, prio_a, prio_b, out);
}